// round 10
// baseline (speedup 1.0000x reference)
#include <cuda_runtime.h>
#include <cuda_bf16.h>
#include <math.h>
#include <stdint.h>

#define LV 2048
#define LT 512
#define LTOT 2560
#define D 512
#define H 8
#define DK 64
#define FF 1024

// ---------------- scratch ----------------
__device__ float g_mask[(size_t)LV * LV];
__device__ float g_partial[LV];
__device__ float g_src[(size_t)LTOT * D];
__device__ float g_src2[(size_t)LTOT * D];
__device__ float g_posq[(size_t)LV * D];
__device__ float g_vh[(size_t)LV * D];
__device__ float g_proj[(size_t)LTOT * D];
__device__ float g_vsuf[(size_t)H * 33 * DK];
__device__ uint32_t g_vth[(size_t)H * DK * (LV / 2)];
__device__ uint32_t g_vtl[(size_t)H * DK * (LV / 2)];
__device__ float g_Opart[(size_t)H * 32 * 4 * 64 * 64];
__device__ float g_mpart[(size_t)H * 32 * 4 * 64];
__device__ float g_lpart[(size_t)H * 32 * 4 * 64];
// pre-split bf16 operands
__device__ __nv_bfloat16 g_qinh[(size_t)LV * D], g_qinl[(size_t)LV * D];
__device__ __nv_bfloat16 g_kinh[(size_t)LV * D], g_kinl[(size_t)LV * D];
__device__ __nv_bfloat16 g_qhh[(size_t)LV * D], g_qhl[(size_t)LV * D];
__device__ __nv_bfloat16 g_khh[(size_t)LV * D], g_khl[(size_t)LV * D];
__device__ __nv_bfloat16 g_s2h[(size_t)LTOT * D], g_s2l[(size_t)LTOT * D];
__device__ __nv_bfloat16 g_atth[(size_t)LV * D], g_attl[(size_t)LV * D];
__device__ __nv_bfloat16 g_ffnh[(size_t)LTOT * FF], g_ffnl[(size_t)LTOT * FF];
// pre-split weights
__device__ __nv_bfloat16 g_wqh[D * D], g_wql[D * D];
__device__ __nv_bfloat16 g_wkh[D * D], g_wkl[D * D];
__device__ __nv_bfloat16 g_wvh[D * D], g_wvl[D * D];
__device__ __nv_bfloat16 g_woh[D * D], g_wol[D * D];
__device__ __nv_bfloat16 g_l1h[FF * D], g_l1l[FF * D];
__device__ __nv_bfloat16 g_l2h[D * FF], g_l2l[D * FF];

// ---------------- helpers ----------------
__device__ __forceinline__ float blk_sum(float v, float* sh) {
    int lane = threadIdx.x & 31, wid = threadIdx.x >> 5;
#pragma unroll
    for (int o = 16; o; o >>= 1) v += __shfl_xor_sync(0xffffffffu, v, o);
    if (lane == 0) sh[wid] = v;
    __syncthreads();
    if (threadIdx.x < 32) {
        float t = (threadIdx.x < 8) ? sh[threadIdx.x] : 0.f;
#pragma unroll
        for (int o = 4; o; o >>= 1) t += __shfl_xor_sync(0xffffffffu, t, o);
        if (threadIdx.x == 0) sh[0] = t;
    }
    __syncthreads();
    float r = sh[0];
    __syncthreads();
    return r;
}

__device__ __forceinline__ void split2(float x, float y, uint32_t& hi, uint32_t& lo) {
    __nv_bfloat16 hx = __float2bfloat16_rn(x), hy = __float2bfloat16_rn(y);
    float lx = x - __bfloat162float(hx), ly = y - __bfloat162float(hy);
    __nv_bfloat162 hp = __halves2bfloat162(hx, hy);
    __nv_bfloat162 lp = __halves2bfloat162(__float2bfloat16_rn(lx), __float2bfloat16_rn(ly));
    hi = *(uint32_t*)&hp;
    lo = *(uint32_t*)&lp;
}

__device__ __forceinline__ void mma_bf16(float* d, uint32_t a0, uint32_t a1, uint32_t a2,
                                         uint32_t a3, uint32_t b0, uint32_t b1) {
    asm volatile(
        "mma.sync.aligned.m16n8k16.row.col.f32.bf16.bf16.f32 "
        "{%0,%1,%2,%3}, {%4,%5,%6,%7}, {%8,%9}, {%0,%1,%2,%3};"
        : "+f"(d[0]), "+f"(d[1]), "+f"(d[2]), "+f"(d[3])
        : "r"(a0), "r"(a1), "r"(a2), "r"(a3), "r"(b0), "r"(b1));
}

// ---------------- mask + loss ----------------
__global__ void k_mask(const float* __restrict__ learn) {
    int n = blockIdx.x;
    __shared__ float sh[32];
    const float L2G = -0.15200309344504997f;
    float psum = 0.f;
    for (int m = threadIdx.x; m < LV; m += 256) {
        float lw = learn[(size_t)n * LV + m];
        float sig = 1.f / (1.f + expf(-lw));
        float maskv;
        if (m == n) maskv = 1.f;
        else if (n > m) { maskv = exp2f((float)(n - m) * L2G) * sig; psum += sig; }
        else { maskv = 0.f; psum += sig; }
        g_mask[(size_t)n * LV + m] = maskv;
    }
    float t = blk_sum(psum, sh);
    if (threadIdx.x == 0) g_partial[n] = t;
}

__global__ void k_loss(float* out, int out_size) {
    __shared__ float sh[32];
    float s = 0.f;
    for (int i = threadIdx.x; i < LV; i += 256) s += g_partial[i];
    s = blk_sum(s, sh);
    if (threadIdx.x == 0 && out_size > LV * D + LT * D)
        out[(size_t)LV * D + (size_t)LT * D] = s / ((float)LV * (float)LV);
}

// ---------------- weight split ----------------
__global__ void k_wsplit(const float* wq, const float* wk, const float* wv, const float* wo,
                         const float* l1, const float* l2) {
    int seg = blockIdx.y;
    const float* src;
    __nv_bfloat16 *dh, *dl;
    int n;
    switch (seg) {
        case 0: src = wq; dh = g_wqh; dl = g_wql; n = D * D; break;
        case 1: src = wk; dh = g_wkh; dl = g_wkl; n = D * D; break;
        case 2: src = wv; dh = g_wvh; dl = g_wvl; n = D * D; break;
        case 3: src = wo; dh = g_woh; dl = g_wol; n = D * D; break;
        case 4: src = l1; dh = g_l1h; dl = g_l1l; n = FF * D; break;
        default: src = l2; dh = g_l2h; dl = g_l2l; n = D * FF; break;
    }
    int i = (blockIdx.x * 256 + threadIdx.x) * 2;
    if (i < n) {
        float2 v = *(const float2*)(src + i);
        uint32_t hi, lo;
        split2(v.x, v.y, hi, lo);
        *(uint32_t*)&dh[i] = hi;
        *(uint32_t*)&dl[i] = lo;
    }
}

// ---------------- concat + LN1 (thread owns adjacent pair) ----------------
__global__ void k_ln1(const float* __restrict__ vid, const float* __restrict__ txt,
                      const float* __restrict__ w, const float* __restrict__ b) {
    int r = blockIdx.x;
    const float* x = (r < LV) ? (vid + (size_t)r * D) : (txt + (size_t)(r - LV) * D);
    __shared__ float sh[32];
    int i0 = threadIdx.x * 2;
    float2 v = *(const float2*)(x + i0);
    float s = blk_sum(v.x + v.y, sh);
    float s2 = blk_sum(v.x * v.x + v.y * v.y, sh);
    float mu = s * (1.f / D);
    float var = s2 * (1.f / D) - mu * mu;
    float inv = rsqrtf(var + 1e-5f);
    size_t o = (size_t)r * D;
    *(float2*)(g_src + o + i0) = v;
    float n0 = (v.x - mu) * inv * w[i0] + b[i0];
    float n1 = (v.y - mu) * inv * w[i0 + 1] + b[i0 + 1];
    *(float2*)(g_src2 + o + i0) = make_float2(n0, n1);
    uint32_t hi, lo;
    split2(n0, n1, hi, lo);
    *(uint32_t*)&g_s2h[o + i0] = hi;
    *(uint32_t*)&g_s2l[o + i0] = lo;
}

// ---------------- xpos + q/k inputs (split output) ----------------
__global__ void k_pos(const float* __restrict__ vid) {
    int r = blockIdx.x;
    int j = threadIdx.x;
    const float L2_1E4 = 13.287712379549449f;
    float sj = (2.f * (float)j + 204.8f) / 716.8f;
    float scale = exp2f(((float)r / 512.f) * log2f(sj));
    float invf = exp2f(-((float)j / 256.f) * L2_1E4);
    float ang = (float)r * invf;
    float sn, cs;
    sincosf(ang, &sn, &cs);
    size_t o = (size_t)r * D + 2 * j;
    float x0 = vid[o], x1 = vid[o + 1];
    float cq = cs * scale, sq = sn * scale;
    float pq0 = x0 * cq - x1 * sq;
    float pq1 = x1 * cq + x0 * sq;
    float iscale = 1.f / scale;
    float ck = cs * iscale, sk = sn * iscale;
    float pk0 = x0 * ck - x1 * sk;
    float pk1 = x1 * ck + x0 * sk;
    g_posq[o] = pq0; g_posq[o + 1] = pq1;
    float n0 = g_src2[o], n1 = g_src2[o + 1];
    uint32_t hi, lo;
    split2(n0 + pq0, n1 + pq1, hi, lo);
    *(uint32_t*)&g_qinh[o] = hi;
    *(uint32_t*)&g_qinl[o] = lo;
    split2(n0 + pk0, n1 + pk1, hi, lo);
    *(uint32_t*)&g_kinh[o] = hi;
    *(uint32_t*)&g_kinl[o] = lo;
}

// ---------------- tensor-core GEMM on pre-split operands ----------------
// mode bit0: write fp32 C; bit1: write split Ch/Cl
__device__ __forceinline__ void gemm_tc(const __nv_bfloat16* __restrict__ Ah_g,
                                        const __nv_bfloat16* __restrict__ Al_g,
                                        const __nv_bfloat16* __restrict__ Bh_g,
                                        const __nv_bfloat16* __restrict__ Bl_g,
                                        const float* __restrict__ bias, float* __restrict__ C,
                                        __nv_bfloat16* __restrict__ Ch,
                                        __nv_bfloat16* __restrict__ Cl,
                                        int N, int K, float alpha, int act, int mode) {
    __shared__ __nv_bfloat16 Ah[128][24], Al[128][24];
    __shared__ __nv_bfloat16 Bh[64][24], Bl[64][24];
    int bm = blockIdx.y * 128, bn = blockIdx.x * 64;
    int t = threadIdx.x, warp = t >> 5, lane = t & 31;
    int gid = lane >> 2, tidg = lane & 3;
    int wm = (warp >> 1) * 32, wn = (warp & 1) * 32;

    int rowA = t >> 1, segA = (t & 1) * 8;
    int rowB = t >> 2, segB = (t & 3) * 4;

    float d[2][4][4];
#pragma unroll
    for (int mt = 0; mt < 2; mt++)
#pragma unroll
        for (int nt = 0; nt < 4; nt++)
#pragma unroll
            for (int r = 0; r < 4; r++) d[mt][nt][r] = 0.f;

    uint4 pah = *(const uint4*)&Ah_g[(size_t)(bm + rowA) * K + segA];
    uint4 pal = *(const uint4*)&Al_g[(size_t)(bm + rowA) * K + segA];
    uint2 pbh = *(const uint2*)&Bh_g[(size_t)(bn + rowB) * K + segB];
    uint2 pbl = *(const uint2*)&Bl_g[(size_t)(bn + rowB) * K + segB];

    for (int k0 = 0; k0 < K; k0 += 16) {
        *(uint4*)&Ah[rowA][segA] = pah;
        *(uint4*)&Al[rowA][segA] = pal;
        *(uint2*)&Bh[rowB][segB] = pbh;
        *(uint2*)&Bl[rowB][segB] = pbl;
        __syncthreads();
        if (k0 + 16 < K) {
            pah = *(const uint4*)&Ah_g[(size_t)(bm + rowA) * K + k0 + 16 + segA];
            pal = *(const uint4*)&Al_g[(size_t)(bm + rowA) * K + k0 + 16 + segA];
            pbh = *(const uint2*)&Bh_g[(size_t)(bn + rowB) * K + k0 + 16 + segB];
            pbl = *(const uint2*)&Bl_g[(size_t)(bn + rowB) * K + k0 + 16 + segB];
        }

        uint32_t ah[2][4], al[2][4];
#pragma unroll
        for (int mt = 0; mt < 2; mt++) {
            int r0 = wm + mt * 16 + gid;
            ah[mt][0] = *(uint32_t*)&Ah[r0][2 * tidg];
            ah[mt][1] = *(uint32_t*)&Ah[r0 + 8][2 * tidg];
            ah[mt][2] = *(uint32_t*)&Ah[r0][8 + 2 * tidg];
            ah[mt][3] = *(uint32_t*)&Ah[r0 + 8][8 + 2 * tidg];
            al[mt][0] = *(uint32_t*)&Al[r0][2 * tidg];
            al[mt][1] = *(uint32_t*)&Al[r0 + 8][2 * tidg];
            al[mt][2] = *(uint32_t*)&Al[r0][8 + 2 * tidg];
            al[mt][3] = *(uint32_t*)&Al[r0 + 8][8 + 2 * tidg];
        }
#pragma unroll
        for (int nt = 0; nt < 4; nt++) {
            int n0 = wn + nt * 8 + gid;
            uint32_t bh0 = *(uint32_t*)&Bh[n0][2 * tidg];
            uint32_t bh1 = *(uint32_t*)&Bh[n0][8 + 2 * tidg];
            uint32_t bl0 = *(uint32_t*)&Bl[n0][2 * tidg];
            uint32_t bl1 = *(uint32_t*)&Bl[n0][8 + 2 * tidg];
#pragma unroll
            for (int mt = 0; mt < 2; mt++) {
                mma_bf16(d[mt][nt], ah[mt][0], ah[mt][1], ah[mt][2], ah[mt][3], bh0, bh1);
                mma_bf16(d[mt][nt], ah[mt][0], ah[mt][1], ah[mt][2], ah[mt][3], bl0, bl1);
                mma_bf16(d[mt][nt], al[mt][0], al[mt][1], al[mt][2], al[mt][3], bh0, bh1);
            }
        }
        __syncthreads();
    }

#pragma unroll
    for (int mt = 0; mt < 2; mt++) {
        int r0 = bm + wm + mt * 16 + gid;
#pragma unroll
        for (int nt = 0; nt < 4; nt++) {
            int c0 = bn + wn + nt * 8 + 2 * tidg;
            float bia0 = bias[c0], bia1 = bias[c0 + 1];
#pragma unroll
            for (int half = 0; half < 2; half++) {
                int row = r0 + half * 8;
                float v0 = (d[mt][nt][half * 2 + 0] + bia0) * alpha;
                float v1 = (d[mt][nt][half * 2 + 1] + bia1) * alpha;
                if (act) {
                    v0 = 0.5f * v0 * (1.f + erff(v0 * 0.70710678118654752f));
                    v1 = 0.5f * v1 * (1.f + erff(v1 * 0.70710678118654752f));
                }
                if (mode & 1) {
                    C[(size_t)row * N + c0] = v0;
                    C[(size_t)row * N + c0 + 1] = v1;
                }
                if (mode & 2) {
                    uint32_t hi, lo;
                    split2(v0, v1, hi, lo);
                    *(uint32_t*)&Ch[(size_t)row * N + c0] = hi;
                    *(uint32_t*)&Cl[(size_t)row * N + c0] = lo;
                }
            }
        }
    }
}

__global__ void __launch_bounds__(256) k_gemm_qkv(const float* bq, const float* bk,
                                                  const float* bv) {
    int z = blockIdx.z;
    if (z == 0)
        gemm_tc(g_qinh, g_qinl, g_wqh, g_wql, bq, nullptr, g_qhh, g_qhl, D, D, 0.125f, 0, 2);
    else if (z == 1)
        gemm_tc(g_kinh, g_kinl, g_wkh, g_wkl, bk, nullptr, g_khh, g_khl, D, D, 1.f, 0, 2);
    else
        gemm_tc(g_s2h, g_s2l, g_wvh, g_wvl, bv, g_vh, nullptr, nullptr, D, D, 1.f, 0, 1);
}
__global__ void __launch_bounds__(256) k_gemm_o(const float* b) {
    gemm_tc(g_atth, g_attl, g_woh, g_wol, b, g_proj, nullptr, nullptr, D, D, 1.f, 0, 1);
}
__global__ void __launch_bounds__(256) k_gemm_f1(const float* b) {
    gemm_tc(g_s2h, g_s2l, g_l1h, g_l1l, b, nullptr, g_ffnh, g_ffnl, FF, D, 1.f, 1, 2);
}
__global__ void __launch_bounds__(256) k_gemm_f2(const float* b) {
    gemm_tc(g_ffnh, g_ffnl, g_l2h, g_l2l, b, g_proj, nullptr, nullptr, D, FF, 1.f, 0, 1);
}

// ---------------- V suffix sums ----------------
__global__ void k_vsuf() {
    int tb = blockIdx.x + 1;
    int h = blockIdx.y;
    int d = threadIdx.x & 63, rg = threadIdx.x >> 6;
    float s = 0.f;
    for (int m = tb * 64 + rg; m < LV; m += 4)
        s += g_vh[(size_t)m * D + h * DK + d];
    __shared__ float sh[4][64];
    sh[rg][d] = s;
    __syncthreads();
    if (rg == 0)
        g_vsuf[((size_t)h * 33 + tb) * DK + d] = sh[0][d] + sh[1][d] + sh[2][d] + sh[3][d];
}

// ---------------- V split + transpose ----------------
__global__ void k_vtrans() {
    __shared__ float vs[64][65];
    int m0 = blockIdx.x * 64, h = blockIdx.y;
    int t = threadIdx.x;
#pragma unroll
    for (int l = 0; l < 16; l++) {
        int idx = t + l * 256;
        int r = idx >> 6, c = idx & 63;
        vs[r][c] = g_vh[(size_t)(m0 + r) * D + h * DK + c];
    }
    __syncthreads();
    int n = t >> 2, j0 = (t & 3) * 8;
    size_t base = ((size_t)h * DK + n) * (LV / 2) + m0 / 2;
#pragma unroll
    for (int i = 0; i < 8; i++) {
        int j = j0 + i;
        uint32_t hi, lo;
        split2(vs[2 * j][n], vs[2 * j + 1][n], hi, lo);
        g_vth[base + j] = hi;
        g_vtl[base + j] = lo;
    }
}

// ---------------- split-K tensor-core flash attention ----------------
#define SS_STR 68
#define KP_STR 72
#define VT_STR 36
#define SS_OFF 0
#define KH_OFF 4352
#define KL_OFF 6656
#define PH_OFF 8960
#define PL_OFF 11264
#define VH_OFF 13568
#define VL_OFF 15872
#define MS_OFF 18176
#define LS_OFF 18240
#define SC_OFF 18304
#define FL_SMEM_BYTES ((SC_OFF + 64) * 4)

__global__ void __launch_bounds__(256) k_flash_chunk() {
    extern __shared__ float sm[];
    float* Ss = sm + SS_OFF;
    __nv_bfloat16* Kh = (__nv_bfloat16*)(sm + KH_OFF);
    __nv_bfloat16* Kl = (__nv_bfloat16*)(sm + KL_OFF);
    __nv_bfloat16* Ph = (__nv_bfloat16*)(sm + PH_OFF);
    __nv_bfloat16* Pl = (__nv_bfloat16*)(sm + PL_OFF);
    uint32_t* Vh = (uint32_t*)(sm + VH_OFF);
    uint32_t* Vl = (uint32_t*)(sm + VL_OFF);
    float* m_s = sm + MS_OFF;
    float* l_s = sm + LS_OFF;
    float* sc_s = sm + SC_OFF;

    int h = blockIdx.y;
    int c = blockIdx.x;
    int rt, ci;
    if (c < 8) { rt = c; ci = 0; }
    else if (c < 24) { rt = 8 + (c - 8) / 2; ci = (c - 8) % 2; }
    else if (c < 48) { rt = 16 + (c - 24) / 3; ci = (c - 24) % 3; }
    else { rt = 24 + (c - 48) / 4; ci = (c - 48) % 4; }
    int nch = rt / 8 + 1;
    int ntot = rt + 1;
    int tpc = (ntot + nch - 1) / nch;
    int tile0 = ci * tpc;
    int tile1 = min(tile0 + tpc, ntot);
    int bm = rt * 64;

    int t = threadIdx.x;
    int warp = t >> 5, lane = t & 31;
    int gid = lane >> 2, tidg = lane & 3;
    int wm = (warp >> 1) * 16, wn = (warp & 1) * 32;

    // stage pre-split Q tile into Ph/Pl, then pull fragments
#pragma unroll
    for (int l = 0; l < 4; l++) {
        int idx = t + l * 256;
        int r = idx >> 4, c4 = (idx & 15) << 2;
        *(uint2*)&Ph[r * KP_STR + c4] = *(const uint2*)&g_qhh[(size_t)(bm + r) * D + h * DK + c4];
        *(uint2*)&Pl[r * KP_STR + c4] = *(const uint2*)&g_qhl[(size_t)(bm + r) * D + h * DK + c4];
    }
    if (t < 64) { m_s[t] = -1e30f; l_s[t] = 0.f; }
    __syncthreads();

    uint32_t qh[4][4], ql[4][4];
    {
        int r1 = (wm + gid) * KP_STR, r2 = (wm + gid + 8) * KP_STR;
#pragma unroll
        for (int kc = 0; kc < 4; kc++) {
            int k0 = kc * 16;
            qh[kc][0] = *(uint32_t*)&Ph[r1 + k0 + 2 * tidg];
            qh[kc][1] = *(uint32_t*)&Ph[r2 + k0 + 2 * tidg];
            qh[kc][2] = *(uint32_t*)&Ph[r1 + k0 + 8 + 2 * tidg];
            qh[kc][3] = *(uint32_t*)&Ph[r2 + k0 + 8 + 2 * tidg];
            ql[kc][0] = *(uint32_t*)&Pl[r1 + k0 + 2 * tidg];
            ql[kc][1] = *(uint32_t*)&Pl[r2 + k0 + 2 * tidg];
            ql[kc][2] = *(uint32_t*)&Pl[r1 + k0 + 8 + 2 * tidg];
            ql[kc][3] = *(uint32_t*)&Pl[r2 + k0 + 8 + 2 * tidg];
        }
    }

    float acc[4][4];
#pragma unroll
    for (int nt = 0; nt < 4; nt++)
#pragma unroll
        for (int r = 0; r < 4; r++) acc[nt][r] = 0.f;

    for (int tile = tile0; tile < tile1; tile++) {
        int m0 = tile * 64;
        __syncthreads();
        // K tile: pure copy of pre-split bf16
#pragma unroll
        for (int l = 0; l < 4; l++) {
            int idx = t + l * 256;
            int r = idx >> 4, c4 = (idx & 15) << 2;
            *(uint2*)&Kh[r * KP_STR + c4] =
                *(const uint2*)&g_khh[(size_t)(m0 + r) * D + h * DK + c4];
            *(uint2*)&Kl[r * KP_STR + c4] =
                *(const uint2*)&g_khl[(size_t)(m0 + r) * D + h * DK + c4];
        }
        {
            int n = t >> 2, j0 = (t & 3) * 8;
            size_t base = ((size_t)h * DK + n) * (LV / 2) + m0 / 2;
#pragma unroll
            for (int i = 0; i < 8; i++) {
                Vh[n * VT_STR + j0 + i] = g_vth[base + j0 + i];
                Vl[n * VT_STR + j0 + i] = g_vtl[base + j0 + i];
            }
        }
        __syncthreads();

        // S = Q K^T (3-term bf16)
        float sfr[4][4];
#pragma unroll
        for (int nt = 0; nt < 4; nt++)
#pragma unroll
            for (int r = 0; r < 4; r++) sfr[nt][r] = 0.f;
#pragma unroll
        for (int kc = 0; kc < 4; kc++) {
            int k0 = kc * 16;
#pragma unroll
            for (int nt = 0; nt < 4; nt++) {
                int n0 = (wn + nt * 8 + gid) * KP_STR;
                uint32_t bh0 = *(uint32_t*)&Kh[n0 + k0 + 2 * tidg];
                uint32_t bh1 = *(uint32_t*)&Kh[n0 + k0 + 8 + 2 * tidg];
                uint32_t bl0 = *(uint32_t*)&Kl[n0 + k0 + 2 * tidg];
                uint32_t bl1 = *(uint32_t*)&Kl[n0 + k0 + 8 + 2 * tidg];
                mma_bf16(sfr[nt], qh[kc][0], qh[kc][1], qh[kc][2], qh[kc][3], bh0, bh1);
                mma_bf16(sfr[nt], qh[kc][0], qh[kc][1], qh[kc][2], qh[kc][3], bl0, bl1);
                mma_bf16(sfr[nt], ql[kc][0], ql[kc][1], ql[kc][2], ql[kc][3], bh0, bh1);
            }
        }
#pragma unroll
        for (int nt = 0; nt < 4; nt++) {
            int c0 = wn + nt * 8 + 2 * tidg;
            Ss[(wm + gid) * SS_STR + c0] = sfr[nt][0];
            Ss[(wm + gid) * SS_STR + c0 + 1] = sfr[nt][1];
            Ss[(wm + gid + 8) * SS_STR + c0] = sfr[nt][2];
            Ss[(wm + gid + 8) * SS_STR + c0 + 1] = sfr[nt][3];
        }
        __syncthreads();

        // softmax: 4 threads per row; write P split bf16
        {
            int row = t >> 2, seg = t & 3;
            float* rp = Ss + row * SS_STR + seg * 16;
            const float* mp = g_mask + (size_t)(bm + row) * LV + m0 + seg * 16;
            float x[16];
#pragma unroll
            for (int q4 = 0; q4 < 4; q4++) {
                float4 xv = *(float4*)(rp + q4 * 4);
                float4 mv = *(const float4*)(mp + q4 * 4);
                x[q4 * 4 + 0] = xv.x * mv.x;
                x[q4 * 4 + 1] = xv.y * mv.y;
                x[q4 * 4 + 2] = xv.z * mv.z;
                x[q4 * 4 + 3] = xv.w * mv.w;
            }
            float mx = x[0];
#pragma unroll
            for (int i = 1; i < 16; i++) mx = fmaxf(mx, x[i]);
            mx = fmaxf(mx, __shfl_xor_sync(0xffffffffu, mx, 1));
            mx = fmaxf(mx, __shfl_xor_sync(0xffffffffu, mx, 2));
            float m_old = m_s[row];
            float m_new = fmaxf(m_old, mx);
            float sum = 0.f;
#pragma unroll
            for (int i = 0; i < 16; i++) {
                x[i] = __expf(x[i] - m_new);
                sum += x[i];
            }
            sum += __shfl_xor_sync(0xffffffffu, sum, 1);
            sum += __shfl_xor_sync(0xffffffffu, sum, 2);
            float scl = __expf(m_old - m_new);
            int pb = row * KP_STR + seg * 16;
#pragma unroll
            for (int i = 0; i < 8; i++) {
                uint32_t hi, lo;
                split2(x[2 * i], x[2 * i + 1], hi, lo);
                *(uint32_t*)&Ph[pb + 2 * i] = hi;
                *(uint32_t*)&Pl[pb + 2 * i] = lo;
            }
            if (seg == 0) {
                m_s[row] = m_new;
                l_s[row] = l_s[row] * scl + sum;
                sc_s[row] = scl;
            }
        }
        __syncthreads();

        // rescale O, then O += P V
        {
            float s1 = sc_s[wm + gid], s2 = sc_s[wm + gid + 8];
#pragma unroll
            for (int nt = 0; nt < 4; nt++) {
                acc[nt][0] *= s1; acc[nt][1] *= s1;
                acc[nt][2] *= s2; acc[nt][3] *= s2;
            }
        }
#pragma unroll
        for (int kc = 0; kc < 4; kc++) {
            int k0 = kc * 16;
            int r1 = (wm + gid) * KP_STR, r2 = (wm + gid + 8) * KP_STR;
            uint32_t ah0 = *(uint32_t*)&Ph[r1 + k0 + 2 * tidg];
            uint32_t ah1 = *(uint32_t*)&Ph[r2 + k0 + 2 * tidg];
            uint32_t ah2 = *(uint32_t*)&Ph[r1 + k0 + 8 + 2 * tidg];
            uint32_t ah3 = *(uint32_t*)&Ph[r2 + k0 + 8 + 2 * tidg];
            uint32_t al0 = *(uint32_t*)&Pl[r1 + k0 + 2 * tidg];
            uint32_t al1 = *(uint32_t*)&Pl[r2 + k0 + 2 * tidg];
            uint32_t al2 = *(uint32_t*)&Pl[r1 + k0 + 8 + 2 * tidg];
            uint32_t al3 = *(uint32_t*)&Pl[r2 + k0 + 8 + 2 * tidg];
#pragma unroll
            for (int nt = 0; nt < 4; nt++) {
                int n0 = (wn + nt * 8 + gid) * VT_STR + k0 / 2;
                uint32_t bh0 = Vh[n0 + tidg];
                uint32_t bh1 = Vh[n0 + 4 + tidg];
                uint32_t bl0 = Vl[n0 + tidg];
                uint32_t bl1 = Vl[n0 + 4 + tidg];
                mma_bf16(acc[nt], ah0, ah1, ah2, ah3, bh0, bh1);
                mma_bf16(acc[nt], ah0, ah1, ah2, ah3, bl0, bl1);
                mma_bf16(acc[nt], al0, al1, al2, al3, bh0, bh1);
            }
        }
    }
    __syncthreads();

    size_t obase = (((size_t)h * 32 + rt) * 4 + ci) * 4096;
    int r1 = wm + gid, r2 = wm + gid + 8;
#pragma unroll
    for (int nt = 0; nt < 4; nt++) {
        int c0 = wn + nt * 8 + 2 * tidg;
        g_Opart[obase + r1 * 64 + c0] = acc[nt][0];
        g_Opart[obase + r1 * 64 + c0 + 1] = acc[nt][1];
        g_Opart[obase + r2 * 64 + c0] = acc[nt][2];
        g_Opart[obase + r2 * 64 + c0 + 1] = acc[nt][3];
    }
    if (t < 64) {
        size_t mbase = (((size_t)h * 32 + rt) * 4 + ci) * 64 + t;
        g_mpart[mbase] = m_s[t];
        g_lpart[mbase] = l_s[t];
    }
}

// ---------------- merge partials + tail + normalize (split output) ----------------
__global__ void __launch_bounds__(256) k_fmerge() {
    int rt = blockIdx.x, h = blockIdx.y;
    int nch = rt / 8 + 1;
    int bm = rt * 64;
    int t = threadIdx.x;
    int row = t >> 2, seg = t & 3;

    size_t pbase = ((size_t)h * 32 + rt) * 4;
    float mv[4], lv[4];
    float mstar = -1e30f;
#pragma unroll
    for (int ci = 0; ci < 4; ci++) {
        if (ci < nch) {
            mv[ci] = g_mpart[(pbase + ci) * 64 + row];
            lv[ci] = g_lpart[(pbase + ci) * 64 + row];
            mstar = fmaxf(mstar, mv[ci]);
        }
    }
    float p0 = __expf(-mstar);
    float nz = (float)(LV - (bm + 64));
    float lstar = nz * p0;
    float w[4];
#pragma unroll
    for (int ci = 0; ci < 4; ci++) {
        if (ci < nch) {
            w[ci] = __expf(mv[ci] - mstar);
            lstar += lv[ci] * w[ci];
        }
    }
    float inv = 1.f / lstar;

    int tb = rt + 1;
    const float* suf = g_vsuf + ((size_t)h * 33 + tb) * DK + seg * 16;
    float o[16];
#pragma unroll
    for (int q4 = 0; q4 < 4; q4++) {
        float4 sv = *(const float4*)(suf + q4 * 4);
        o[q4 * 4 + 0] = p0 * sv.x;
        o[q4 * 4 + 1] = p0 * sv.y;
        o[q4 * 4 + 2] = p0 * sv.z;
        o[q4 * 4 + 3] = p0 * sv.w;
    }
#pragma unroll
    for (int ci = 0; ci < 4; ci++) {
        if (ci < nch) {
            const float* op = g_Opart + (pbase + ci) * 4096 + row * 64 + seg * 16;
            float wc = w[ci];
#pragma unroll
            for (int q4 = 0; q4 < 4; q4++) {
                float4 ov = *(const float4*)(op + q4 * 4);
                o[q4 * 4 + 0] += wc * ov.x;
                o[q4 * 4 + 1] += wc * ov.y;
                o[q4 * 4 + 2] += wc * ov.z;
                o[q4 * 4 + 3] += wc * ov.w;
            }
        }
    }
    size_t dst = (size_t)(bm + row) * D + h * DK + seg * 16;
#pragma unroll
    for (int i = 0; i < 8; i++) {
        uint32_t hi, lo;
        split2(o[2 * i] * inv, o[2 * i + 1] * inv, hi, lo);
        *(uint32_t*)&g_atth[dst + 2 * i] = hi;
        *(uint32_t*)&g_attl[dst + 2 * i] = lo;
    }
}

// ---------------- residual + pos + LN2 ----------------
__global__ void k_res_ln2(const float* __restrict__ w, const float* __restrict__ b) {
    int r = blockIdx.x;
    __shared__ float sh[32];
    int i0 = threadIdx.x * 2;
    size_t o = (size_t)r * D;
    float v0, v1;
    if (r < LV) {
        v0 = g_src[o + i0] + g_proj[o + i0] + g_posq[o + i0];
        v1 = g_src[o + i0 + 1] + g_proj[o + i0 + 1] + g_posq[o + i0 + 1];
    } else {
        int tt = r - LV;
        float xe = (float)(tt + 1) / (512.f + 1e-6f) * 6.283185307179586f;
        const float L2_1E4 = 13.287712379549449f;
        float dim = exp2f(((float)threadIdx.x / 256.f) * L2_1E4);
        float val = xe / dim;
        float sn, cs;
        sincosf(val, &sn, &cs);
        v0 = g_src[o + i0] + g_src2[o + i0] + sn;
        v1 = g_src[o + i0 + 1] + g_src2[o + i0 + 1] + cs;
    }
    float s = blk_sum(v0 + v1, sh);
    float s2 = blk_sum(v0 * v0 + v1 * v1, sh);
    float mu = s * (1.f / D);
    float var = s2 * (1.f / D) - mu * mu;
    float inv = rsqrtf(var + 1e-5f);
    g_src[o + i0] = v0;
    g_src[o + i0 + 1] = v1;
    float n0 = (v0 - mu) * inv * w[i0] + b[i0];
    float n1 = (v1 - mu) * inv * w[i0 + 1] + b[i0 + 1];
    *(float2*)(g_src2 + o + i0) = make_float2(n0, n1);
    uint32_t hi, lo;
    split2(n0, n1, hi, lo);
    *(uint32_t*)&g_s2h[o + i0] = hi;
    *(uint32_t*)&g_s2l[o + i0] = lo;
}

// ---------------- residual + LN3 + output ----------------
__global__ void k_res_ln3(const float* __restrict__ w, const float* __restrict__ b,
                          float* __restrict__ out) {
    int r = blockIdx.x;
    __shared__ float sh[32];
    int i0 = threadIdx.x, i1 = threadIdx.x + 256;
    size_t o = (size_t)r * D;
    float v0 = g_src[o + i0] + g_proj[o + i0];
    float v1 = g_src[o + i1] + g_proj[o + i1];
    float s = blk_sum(v0 + v1, sh);
    float s2 = blk_sum(v0 * v0 + v1 * v1, sh);
    float mu = s * (1.f / D);
    float var = s2 * (1.f / D) - mu * mu;
    float inv = rsqrtf(var + 1e-5f);
    out[o + i0] = (v0 - mu) * inv * w[i0] + b[i0];
    out[o + i1] = (v1 - mu) * inv * w[i1] + b[i1];
}

extern "C" void kernel_launch(void* const* d_in, const int* in_sizes, int n_in,
                              void* d_out, int out_size) {
    const float* src_vid = (const float*)d_in[0];
    const float* src_txt = (const float*)d_in[1];
    const float* ln1_w = (const float*)d_in[2];
    const float* ln1_b = (const float*)d_in[3];
    const float* wq = (const float*)d_in[4];
    const float* bq = (const float*)d_in[5];
    const float* wk = (const float*)d_in[6];
    const float* bk = (const float*)d_in[7];
    const float* wv = (const float*)d_in[8];
    const float* bv = (const float*)d_in[9];
    const float* wo = (const float*)d_in[10];
    const float* bo = (const float*)d_in[11];
    const float* lin1_w = (const float*)d_in[12];
    const float* lin1_b = (const float*)d_in[13];
    const float* lin2_w = (const float*)d_in[14];
    const float* lin2_b = (const float*)d_in[15];
    const float* ln2_w = (const float*)d_in[16];
    const float* ln2_b = (const float*)d_in[17];
    const float* ln3_w = (const float*)d_in[18];
    const float* ln3_b = (const float*)d_in[19];
    const float* learn = (const float*)d_in[20];
    float* out = (float*)d_out;

    cudaFuncSetAttribute(k_flash_chunk, cudaFuncAttributeMaxDynamicSharedMemorySize,
                         FL_SMEM_BYTES);

    k_wsplit<<<dim3((FF * D / 2 + 255) / 256, 6), 256>>>(wq, wk, wv, wo, lin1_w, lin2_w);
    k_mask<<<LV, 256>>>(learn);
    k_loss<<<1, 256>>>(out, out_size);
    k_ln1<<<LTOT, 256>>>(src_vid, src_txt, ln1_w, ln1_b);
    k_pos<<<LV, 256>>>(src_vid);

    k_gemm_qkv<<<dim3(D / 64, LV / 128, 3), 256>>>(bq, bk, bv);

    k_vsuf<<<dim3(32, H), 256>>>();
    k_vtrans<<<dim3(LV / 64, H), 256>>>();
    k_flash_chunk<<<dim3(80, H), 256, FL_SMEM_BYTES>>>();
    k_fmerge<<<dim3(32, H), 256>>>();

    k_gemm_o<<<dim3(D / 64, LV / 128), 256>>>(bo);
    k_res_ln2<<<LTOT, 256>>>(ln2_w, ln2_b);

    k_gemm_f1<<<dim3(FF / 64, LTOT / 128), 256>>>(lin1_b);
    k_gemm_f2<<<dim3(D / 64, LTOT / 128), 256>>>(lin2_b);

    k_res_ln3<<<LTOT, 256>>>(ln3_w, ln3_b, out);
}

// round 16
// speedup vs baseline: 1.1187x; 1.1187x over previous
#include <cuda_runtime.h>
#include <cuda_bf16.h>
#include <math.h>
#include <stdint.h>

#define LV 2048
#define LT 512
#define LTOT 2560
#define D 512
#define H 8
#define DK 64
#define FF 1024

// ---------------- scratch ----------------
__device__ float g_mask[(size_t)LV * LV];
__device__ float g_partial[LV];
__device__ float g_src[(size_t)LTOT * D];
__device__ float g_src2[(size_t)LTOT * D];
__device__ float g_posq[(size_t)LV * D];
__device__ float g_qin[(size_t)LV * D];
__device__ float g_kin[(size_t)LV * D];
__device__ float g_qh[(size_t)LV * D];
__device__ float g_kh[(size_t)LV * D];
__device__ float g_vh[(size_t)LV * D];
__device__ float g_att[(size_t)LV * D];
__device__ float g_proj[(size_t)LTOT * D];
__device__ float g_ffn[(size_t)LTOT * FF];
__device__ float g_vsuf[(size_t)H * 33 * DK];
__device__ uint32_t g_vth[(size_t)H * DK * (LV / 2)];
__device__ uint32_t g_vtl[(size_t)H * DK * (LV / 2)];
__device__ float g_Opart[(size_t)H * 32 * 4 * 64 * 64];
__device__ float g_mpart[(size_t)H * 32 * 4 * 64];
__device__ float g_lpart[(size_t)H * 32 * 4 * 64];

// ---------------- block reductions (blockDim.x == 256) ----------------
__device__ __forceinline__ float blk_sum(float v, float* sh) {
    int lane = threadIdx.x & 31, wid = threadIdx.x >> 5;
#pragma unroll
    for (int o = 16; o; o >>= 1) v += __shfl_xor_sync(0xffffffffu, v, o);
    if (lane == 0) sh[wid] = v;
    __syncthreads();
    if (threadIdx.x < 32) {
        float t = (threadIdx.x < 8) ? sh[threadIdx.x] : 0.f;
#pragma unroll
        for (int o = 4; o; o >>= 1) t += __shfl_xor_sync(0xffffffffu, t, o);
        if (threadIdx.x == 0) sh[0] = t;
    }
    __syncthreads();
    float r = sh[0];
    __syncthreads();
    return r;
}

// ---------------- mask + sparsity-loss partials ----------------
__global__ void k_mask(const float* __restrict__ learn) {
    int n = blockIdx.x;
    __shared__ float sh[32];
    const float L2G = -0.15200309344504997f;
    float psum = 0.f;
    for (int m = threadIdx.x; m < LV; m += 256) {
        float lw = learn[(size_t)n * LV + m];
        float sig = 1.f / (1.f + __expf(-lw));
        float maskv;
        if (m == n) {
            maskv = 1.f;
        } else if (n > m) {
            maskv = exp2f((float)(n - m) * L2G) * sig;
            psum += sig;
        } else {
            maskv = 0.f;
            psum += sig;
        }
        g_mask[(size_t)n * LV + m] = maskv;
    }
    float t = blk_sum(psum, sh);
    if (threadIdx.x == 0) g_partial[n] = t;
}

__global__ void k_loss(float* out, int out_size) {
    __shared__ float sh[32];
    float s = 0.f;
    for (int i = threadIdx.x; i < LV; i += 256) s += g_partial[i];
    s = blk_sum(s, sh);
    if (threadIdx.x == 0 && out_size > LV * D + LT * D)
        out[(size_t)LV * D + (size_t)LT * D] = s / ((float)LV * (float)LV);
}

// ---------------- concat + LN1 ----------------
__global__ void k_ln1(const float* __restrict__ vid, const float* __restrict__ txt,
                      const float* __restrict__ w, const float* __restrict__ b) {
    int r = blockIdx.x;
    const float* x = (r < LV) ? (vid + (size_t)r * D) : (txt + (size_t)(r - LV) * D);
    __shared__ float sh[32];
    int i0 = threadIdx.x, i1 = threadIdx.x + 256;
    float v0 = x[i0], v1 = x[i1];
    float s = blk_sum(v0 + v1, sh);
    float s2 = blk_sum(v0 * v0 + v1 * v1, sh);
    float mu = s * (1.f / D);
    float var = s2 * (1.f / D) - mu * mu;
    float inv = rsqrtf(var + 1e-5f);
    size_t o = (size_t)r * D;
    g_src[o + i0] = v0;
    g_src[o + i1] = v1;
    g_src2[o + i0] = (v0 - mu) * inv * w[i0] + b[i0];
    g_src2[o + i1] = (v1 - mu) * inv * w[i1] + b[i1];
}

// ---------------- xpos positional encodings + q/k inputs ----------------
__global__ void k_pos(const float* __restrict__ vid) {
    int r = blockIdx.x;
    int j = threadIdx.x;
    const float L2_1E4 = 13.287712379549449f;
    float sj = (2.f * (float)j + 204.8f) / 716.8f;
    float scale = exp2f(((float)r / 512.f) * log2f(sj));
    float invf = exp2f(-((float)j / 256.f) * L2_1E4);
    float ang = (float)r * invf;
    float sn, cs;
    sincosf(ang, &sn, &cs);
    size_t o = (size_t)r * D + 2 * j;
    float x0 = vid[o], x1 = vid[o + 1];
    float cq = cs * scale, sq = sn * scale;
    float pq0 = x0 * cq - x1 * sq;
    float pq1 = x1 * cq + x0 * sq;
    float iscale = 1.f / scale;
    float ck = cs * iscale, sk = sn * iscale;
    float pk0 = x0 * ck - x1 * sk;
    float pk1 = x1 * ck + x0 * sk;
    g_posq[o] = pq0; g_posq[o + 1] = pq1;
    float n0 = g_src2[o], n1 = g_src2[o + 1];
    g_qin[o] = n0 + pq0; g_qin[o + 1] = n1 + pq1;
    g_kin[o] = n0 + pk0; g_kin[o + 1] = n1 + pk1;
}

// ---------------- bf16 split helpers (packed F2FP path) ----------------
__device__ __forceinline__ void split2(float x, float y, uint32_t& hi, uint32_t& lo) {
    __nv_bfloat162 hp = __float22bfloat162_rn(make_float2(x, y));
    uint32_t h = *(uint32_t*)&hp;
    float fx = __uint_as_float(h << 16);
    float fy = __uint_as_float(h & 0xffff0000u);
    __nv_bfloat162 lp = __float22bfloat162_rn(make_float2(x - fx, y - fy));
    hi = h;
    lo = *(uint32_t*)&lp;
}

__device__ __forceinline__ void mma_bf16(float* d, uint32_t a0, uint32_t a1, uint32_t a2,
                                         uint32_t a3, uint32_t b0, uint32_t b1) {
    asm volatile(
        "mma.sync.aligned.m16n8k16.row.col.f32.bf16.bf16.f32 "
        "{%0,%1,%2,%3}, {%4,%5,%6,%7}, {%8,%9}, {%0,%1,%2,%3};"
        : "+f"(d[0]), "+f"(d[1]), "+f"(d[2]), "+f"(d[3])
        : "r"(a0), "r"(a1), "r"(a2), "r"(a3), "r"(b0), "r"(b1));
}

// ---------------- tensor-core GEMM (bf16 split, register prefetch) ----------------
__device__ __forceinline__ void gemm_tc(const float* __restrict__ A, const float* __restrict__ W,
                                        const float* __restrict__ bias, float* __restrict__ C,
                                        int N, int K, float alpha, int act) {
    __shared__ __nv_bfloat16 Ah[128][24], Al[128][24];
    __shared__ __nv_bfloat16 Bh[64][24], Bl[64][24];
    int bm = blockIdx.y * 128, bn = blockIdx.x * 64;
    int t = threadIdx.x, warp = t >> 5, lane = t & 31;
    int gid = lane >> 2, tidg = lane & 3;
    int wm = (warp >> 1) * 32, wn = (warp & 1) * 32;

    int rowA0 = t >> 2, rowA1 = (t >> 2) + 64, c4 = (t & 3) << 2;
    int rowB = t >> 2;

    float d[2][4][4];
#pragma unroll
    for (int mt = 0; mt < 2; mt++)
#pragma unroll
        for (int nt = 0; nt < 4; nt++)
#pragma unroll
            for (int r = 0; r < 4; r++) d[mt][nt][r] = 0.f;

    float4 pa0 = *(const float4*)(A + (size_t)(bm + rowA0) * K + c4);
    float4 pa1 = *(const float4*)(A + (size_t)(bm + rowA1) * K + c4);
    float4 pb = *(const float4*)(W + (size_t)(bn + rowB) * K + c4);

    for (int k0 = 0; k0 < K; k0 += 16) {
        {
            uint32_t h01, l01, h23, l23;
            split2(pa0.x, pa0.y, h01, l01);
            split2(pa0.z, pa0.w, h23, l23);
            *(uint32_t*)&Ah[rowA0][c4] = h01;
            *(uint32_t*)&Ah[rowA0][c4 + 2] = h23;
            *(uint32_t*)&Al[rowA0][c4] = l01;
            *(uint32_t*)&Al[rowA0][c4 + 2] = l23;
            split2(pa1.x, pa1.y, h01, l01);
            split2(pa1.z, pa1.w, h23, l23);
            *(uint32_t*)&Ah[rowA1][c4] = h01;
            *(uint32_t*)&Ah[rowA1][c4 + 2] = h23;
            *(uint32_t*)&Al[rowA1][c4] = l01;
            *(uint32_t*)&Al[rowA1][c4 + 2] = l23;
            split2(pb.x, pb.y, h01, l01);
            split2(pb.z, pb.w, h23, l23);
            *(uint32_t*)&Bh[rowB][c4] = h01;
            *(uint32_t*)&Bh[rowB][c4 + 2] = h23;
            *(uint32_t*)&Bl[rowB][c4] = l01;
            *(uint32_t*)&Bl[rowB][c4 + 2] = l23;
        }
        __syncthreads();
        if (k0 + 16 < K) {
            pa0 = *(const float4*)(A + (size_t)(bm + rowA0) * K + k0 + 16 + c4);
            pa1 = *(const float4*)(A + (size_t)(bm + rowA1) * K + k0 + 16 + c4);
            pb = *(const float4*)(W + (size_t)(bn + rowB) * K + k0 + 16 + c4);
        }

        uint32_t ah[2][4], al[2][4];
#pragma unroll
        for (int mt = 0; mt < 2; mt++) {
            int r0 = wm + mt * 16 + gid;
            ah[mt][0] = *(uint32_t*)&Ah[r0][2 * tidg];
            ah[mt][1] = *(uint32_t*)&Ah[r0 + 8][2 * tidg];
            ah[mt][2] = *(uint32_t*)&Ah[r0][8 + 2 * tidg];
            ah[mt][3] = *(uint32_t*)&Ah[r0 + 8][8 + 2 * tidg];
            al[mt][0] = *(uint32_t*)&Al[r0][2 * tidg];
            al[mt][1] = *(uint32_t*)&Al[r0 + 8][2 * tidg];
            al[mt][2] = *(uint32_t*)&Al[r0][8 + 2 * tidg];
            al[mt][3] = *(uint32_t*)&Al[r0 + 8][8 + 2 * tidg];
        }
#pragma unroll
        for (int nt = 0; nt < 4; nt++) {
            int n0 = wn + nt * 8 + gid;
            uint32_t bh0 = *(uint32_t*)&Bh[n0][2 * tidg];
            uint32_t bh1 = *(uint32_t*)&Bh[n0][8 + 2 * tidg];
            uint32_t bl0 = *(uint32_t*)&Bl[n0][2 * tidg];
            uint32_t bl1 = *(uint32_t*)&Bl[n0][8 + 2 * tidg];
#pragma unroll
            for (int mt = 0; mt < 2; mt++) {
                mma_bf16(d[mt][nt], ah[mt][0], ah[mt][1], ah[mt][2], ah[mt][3], bh0, bh1);
                mma_bf16(d[mt][nt], ah[mt][0], ah[mt][1], ah[mt][2], ah[mt][3], bl0, bl1);
                mma_bf16(d[mt][nt], al[mt][0], al[mt][1], al[mt][2], al[mt][3], bh0, bh1);
            }
        }
        __syncthreads();
    }

#pragma unroll
    for (int mt = 0; mt < 2; mt++) {
        int r0 = bm + wm + mt * 16 + gid;
#pragma unroll
        for (int nt = 0; nt < 4; nt++) {
            int c0 = bn + wn + nt * 8 + 2 * tidg;
            float bia0 = bias[c0], bia1 = bias[c0 + 1];
#pragma unroll
            for (int half = 0; half < 2; half++) {
                int row = r0 + half * 8;
                float v0 = (d[mt][nt][half * 2 + 0] + bia0) * alpha;
                float v1 = (d[mt][nt][half * 2 + 1] + bia1) * alpha;
                if (act) {
                    v0 = 0.5f * v0 * (1.f + erff(v0 * 0.70710678118654752f));
                    v1 = 0.5f * v1 * (1.f + erff(v1 * 0.70710678118654752f));
                }
                C[(size_t)row * N + c0] = v0;
                C[(size_t)row * N + c0 + 1] = v1;
            }
        }
    }
}

__global__ void __launch_bounds__(256) k_gemm_qkv(const float* wq, const float* bq,
                                                  const float* wk, const float* bk,
                                                  const float* wv, const float* bv) {
    int z = blockIdx.z;
    const float* A = (z == 0) ? g_qin : (z == 1) ? g_kin : g_src2;
    const float* W = (z == 0) ? wq : (z == 1) ? wk : wv;
    const float* B = (z == 0) ? bq : (z == 1) ? bk : bv;
    float* C = (z == 0) ? g_qh : (z == 1) ? g_kh : g_vh;
    float alpha = (z == 0) ? 0.125f : 1.f;
    gemm_tc(A, W, B, C, D, D, alpha, 0);
}
__global__ void __launch_bounds__(256) k_gemm_o(const float* w, const float* b) {
    gemm_tc(g_att, w, b, g_proj, D, D, 1.f, 0);
}
__global__ void __launch_bounds__(256) k_gemm_f1(const float* w, const float* b) {
    gemm_tc(g_src2, w, b, g_ffn, FF, D, 1.f, 1);
}
__global__ void __launch_bounds__(256) k_gemm_f2(const float* w, const float* b) {
    gemm_tc(g_ffn, w, b, g_proj, D, FF, 1.f, 0);
}

// ---------------- V suffix sums ----------------
__global__ void k_vsuf() {
    int tb = blockIdx.x + 1;
    int h = blockIdx.y;
    int d = threadIdx.x & 63, rg = threadIdx.x >> 6;
    float s = 0.f;
    for (int m = tb * 64 + rg; m < LV; m += 4)
        s += g_vh[(size_t)m * D + h * DK + d];
    __shared__ float sh[4][64];
    sh[rg][d] = s;
    __syncthreads();
    if (rg == 0)
        g_vsuf[((size_t)h * 33 + tb) * DK + d] = sh[0][d] + sh[1][d] + sh[2][d] + sh[3][d];
}

// ---------------- V split + transpose ----------------
__global__ void k_vtrans() {
    __shared__ float vs[64][65];
    int m0 = blockIdx.x * 64, h = blockIdx.y;
    int t = threadIdx.x;
#pragma unroll
    for (int l = 0; l < 16; l++) {
        int idx = t + l * 256;
        int r = idx >> 6, c = idx & 63;
        vs[r][c] = g_vh[(size_t)(m0 + r) * D + h * DK + c];
    }
    __syncthreads();
    int n = t >> 2, j0 = (t & 3) * 8;
    size_t base = ((size_t)h * DK + n) * (LV / 2) + m0 / 2;
#pragma unroll
    for (int i = 0; i < 8; i++) {
        int j = j0 + i;
        uint32_t hi, lo;
        split2(vs[2 * j][n], vs[2 * j + 1][n], hi, lo);
        g_vth[base + j] = hi;
        g_vtl[base + j] = lo;
    }
}

// ---------------- split-K tensor-core flash attention ----------------
#define SS_STR 68
#define KP_STR 72
#define VT_STR 36
#define SS_OFF 0
#define KH_OFF 4352
#define KL_OFF 6656
#define PH_OFF 8960
#define PL_OFF 11264
#define VH_OFF 13568
#define VL_OFF 15872
#define MS_OFF 18176
#define LS_OFF 18240
#define SC_OFF 18304
#define FL_SMEM_BYTES ((SC_OFF + 64) * 4)

__global__ void __launch_bounds__(256) k_flash_chunk() {
    extern __shared__ float sm[];
    float* Ss = sm + SS_OFF;
    __nv_bfloat16* Kh = (__nv_bfloat16*)(sm + KH_OFF);
    __nv_bfloat16* Kl = (__nv_bfloat16*)(sm + KL_OFF);
    __nv_bfloat16* Ph = (__nv_bfloat16*)(sm + PH_OFF);
    __nv_bfloat16* Pl = (__nv_bfloat16*)(sm + PL_OFF);
    uint32_t* Vh = (uint32_t*)(sm + VH_OFF);
    uint32_t* Vl = (uint32_t*)(sm + VL_OFF);
    float* m_s = sm + MS_OFF;
    float* l_s = sm + LS_OFF;
    float* sc_s = sm + SC_OFF;

    int h = blockIdx.y;
    int c = blockIdx.x;
    int rt, ci;
    if (c < 8) { rt = c; ci = 0; }
    else if (c < 24) { rt = 8 + (c - 8) / 2; ci = (c - 8) % 2; }
    else if (c < 48) { rt = 16 + (c - 24) / 3; ci = (c - 24) % 3; }
    else { rt = 24 + (c - 48) / 4; ci = (c - 48) % 4; }
    int nch = rt / 8 + 1;
    int ntot = rt + 1;
    int tpc = (ntot + nch - 1) / nch;
    int tile0 = ci * tpc;
    int tile1 = min(tile0 + tpc, ntot);
    int bm = rt * 64;

    int t = threadIdx.x;
    int warp = t >> 5, lane = t & 31;
    int gid = lane >> 2, tidg = lane & 3;
    int wm = (warp >> 1) * 16, wn = (warp & 1) * 32;

    // stage Q tile into Ss, build bf16 hi/lo fragments
#pragma unroll
    for (int l = 0; l < 4; l++) {
        int idx = t + l * 256;
        int r = idx >> 4, c4 = (idx & 15) << 2;
        float4 q = *(const float4*)(g_qh + (size_t)(bm + r) * D + h * DK + c4);
        *(float4*)&Ss[r * SS_STR + c4] = q;
    }
    if (t < 64) { m_s[t] = -1e30f; l_s[t] = 0.f; }
    __syncthreads();

    uint32_t qh[4][4], ql[4][4];
#pragma unroll
    for (int kc = 0; kc < 4; kc++) {
        int k0 = kc * 16;
        int r1 = wm + gid, r2 = r1 + 8;
        split2(Ss[r1 * SS_STR + k0 + 2 * tidg], Ss[r1 * SS_STR + k0 + 2 * tidg + 1],
               qh[kc][0], ql[kc][0]);
        split2(Ss[r2 * SS_STR + k0 + 2 * tidg], Ss[r2 * SS_STR + k0 + 2 * tidg + 1],
               qh[kc][1], ql[kc][1]);
        split2(Ss[r1 * SS_STR + k0 + 8 + 2 * tidg], Ss[r1 * SS_STR + k0 + 8 + 2 * tidg + 1],
               qh[kc][2], ql[kc][2]);
        split2(Ss[r2 * SS_STR + k0 + 8 + 2 * tidg], Ss[r2 * SS_STR + k0 + 8 + 2 * tidg + 1],
               qh[kc][3], ql[kc][3]);
    }

    float acc[4][4];
#pragma unroll
    for (int nt = 0; nt < 4; nt++)
#pragma unroll
        for (int r = 0; r < 4; r++) acc[nt][r] = 0.f;

    for (int tile = tile0; tile < tile1; tile++) {
        int m0 = tile * 64;
        __syncthreads();
#pragma unroll
        for (int l = 0; l < 4; l++) {
            int idx = t + l * 256;
            int r = idx >> 4, c4 = (idx & 15) << 2;
            float4 kv = *(const float4*)(g_kh + (size_t)(m0 + r) * D + h * DK + c4);
            uint32_t h01, l01, h23, l23;
            split2(kv.x, kv.y, h01, l01);
            split2(kv.z, kv.w, h23, l23);
            *(uint32_t*)&Kh[r * KP_STR + c4] = h01;
            *(uint32_t*)&Kh[r * KP_STR + c4 + 2] = h23;
            *(uint32_t*)&Kl[r * KP_STR + c4] = l01;
            *(uint32_t*)&Kl[r * KP_STR + c4 + 2] = l23;
        }
        {
            int n = t >> 2, j0 = (t & 3) * 8;
            size_t base = ((size_t)h * DK + n) * (LV / 2) + m0 / 2;
#pragma unroll
            for (int i = 0; i < 8; i++) {
                Vh[n * VT_STR + j0 + i] = g_vth[base + j0 + i];
                Vl[n * VT_STR + j0 + i] = g_vtl[base + j0 + i];
            }
        }
        __syncthreads();

        // S = Q K^T (3-term bf16)
        float sfr[4][4];
#pragma unroll
        for (int nt = 0; nt < 4; nt++)
#pragma unroll
            for (int r = 0; r < 4; r++) sfr[nt][r] = 0.f;
#pragma unroll
        for (int kc = 0; kc < 4; kc++) {
            int k0 = kc * 16;
#pragma unroll
            for (int nt = 0; nt < 4; nt++) {
                int n0 = (wn + nt * 8 + gid) * KP_STR;
                uint32_t bh0 = *(uint32_t*)&Kh[n0 + k0 + 2 * tidg];
                uint32_t bh1 = *(uint32_t*)&Kh[n0 + k0 + 8 + 2 * tidg];
                uint32_t bl0 = *(uint32_t*)&Kl[n0 + k0 + 2 * tidg];
                uint32_t bl1 = *(uint32_t*)&Kl[n0 + k0 + 8 + 2 * tidg];
                mma_bf16(sfr[nt], qh[kc][0], qh[kc][1], qh[kc][2], qh[kc][3], bh0, bh1);
                mma_bf16(sfr[nt], qh[kc][0], qh[kc][1], qh[kc][2], qh[kc][3], bl0, bl1);
                mma_bf16(sfr[nt], ql[kc][0], ql[kc][1], ql[kc][2], ql[kc][3], bh0, bh1);
            }
        }
#pragma unroll
        for (int nt = 0; nt < 4; nt++) {
            int c0 = wn + nt * 8 + 2 * tidg;
            Ss[(wm + gid) * SS_STR + c0] = sfr[nt][0];
            Ss[(wm + gid) * SS_STR + c0 + 1] = sfr[nt][1];
            Ss[(wm + gid + 8) * SS_STR + c0] = sfr[nt][2];
            Ss[(wm + gid + 8) * SS_STR + c0 + 1] = sfr[nt][3];
        }
        __syncthreads();

        // softmax: 4 threads per row; write P split bf16
        {
            int row = t >> 2, seg = t & 3;
            float* rp = Ss + row * SS_STR + seg * 16;
            const float* mp = g_mask + (size_t)(bm + row) * LV + m0 + seg * 16;
            float x[16];
#pragma unroll
            for (int q4 = 0; q4 < 4; q4++) {
                float4 xv = *(float4*)(rp + q4 * 4);
                float4 mv = *(const float4*)(mp + q4 * 4);
                x[q4 * 4 + 0] = xv.x * mv.x;
                x[q4 * 4 + 1] = xv.y * mv.y;
                x[q4 * 4 + 2] = xv.z * mv.z;
                x[q4 * 4 + 3] = xv.w * mv.w;
            }
            float mx = x[0];
#pragma unroll
            for (int i = 1; i < 16; i++) mx = fmaxf(mx, x[i]);
            mx = fmaxf(mx, __shfl_xor_sync(0xffffffffu, mx, 1));
            mx = fmaxf(mx, __shfl_xor_sync(0xffffffffu, mx, 2));
            float m_old = m_s[row];
            float m_new = fmaxf(m_old, mx);
            float sum = 0.f;
#pragma unroll
            for (int i = 0; i < 16; i++) {
                x[i] = __expf(x[i] - m_new);
                sum += x[i];
            }
            sum += __shfl_xor_sync(0xffffffffu, sum, 1);
            sum += __shfl_xor_sync(0xffffffffu, sum, 2);
            float scl = __expf(m_old - m_new);
            int pb = row * KP_STR + seg * 16;
#pragma unroll
            for (int i = 0; i < 8; i++) {
                uint32_t hi, lo;
                split2(x[2 * i], x[2 * i + 1], hi, lo);
                *(uint32_t*)&Ph[pb + 2 * i] = hi;
                *(uint32_t*)&Pl[pb + 2 * i] = lo;
            }
            if (seg == 0) {
                m_s[row] = m_new;
                l_s[row] = l_s[row] * scl + sum;
                sc_s[row] = scl;
            }
        }
        __syncthreads();

        // rescale O, then O += P V
        {
            float s1 = sc_s[wm + gid], s2 = sc_s[wm + gid + 8];
#pragma unroll
            for (int nt = 0; nt < 4; nt++) {
                acc[nt][0] *= s1; acc[nt][1] *= s1;
                acc[nt][2] *= s2; acc[nt][3] *= s2;
            }
        }
#pragma unroll
        for (int kc = 0; kc < 4; kc++) {
            int k0 = kc * 16;
            int r1 = (wm + gid) * KP_STR, r2 = (wm + gid + 8) * KP_STR;
            uint32_t ah0 = *(uint32_t*)&Ph[r1 + k0 + 2 * tidg];
            uint32_t ah1 = *(uint32_t*)&Ph[r2 + k0 + 2 * tidg];
            uint32_t ah2 = *(uint32_t*)&Ph[r1 + k0 + 8 + 2 * tidg];
            uint32_t ah3 = *(uint32_t*)&Ph[r2 + k0 + 8 + 2 * tidg];
            uint32_t al0 = *(uint32_t*)&Pl[r1 + k0 + 2 * tidg];
            uint32_t al1 = *(uint32_t*)&Pl[r2 + k0 + 2 * tidg];
            uint32_t al2 = *(uint32_t*)&Pl[r1 + k0 + 8 + 2 * tidg];
            uint32_t al3 = *(uint32_t*)&Pl[r2 + k0 + 8 + 2 * tidg];
#pragma unroll
            for (int nt = 0; nt < 4; nt++) {
                int n0 = (wn + nt * 8 + gid) * VT_STR + k0 / 2;
                uint32_t bh0 = Vh[n0 + tidg];
                uint32_t bh1 = Vh[n0 + 4 + tidg];
                uint32_t bl0 = Vl[n0 + tidg];
                uint32_t bl1 = Vl[n0 + 4 + tidg];
                mma_bf16(acc[nt], ah0, ah1, ah2, ah3, bh0, bh1);
                mma_bf16(acc[nt], ah0, ah1, ah2, ah3, bl0, bl1);
                mma_bf16(acc[nt], al0, al1, al2, al3, bh0, bh1);
            }
        }
    }
    __syncthreads();

    // write partials (unnormalized, chunk-local m/l)
    size_t obase = (((size_t)h * 32 + rt) * 4 + ci) * 4096;
    int r1 = wm + gid, r2 = wm + gid + 8;
#pragma unroll
    for (int nt = 0; nt < 4; nt++) {
        int c0 = wn + nt * 8 + 2 * tidg;
        g_Opart[obase + r1 * 64 + c0] = acc[nt][0];
        g_Opart[obase + r1 * 64 + c0 + 1] = acc[nt][1];
        g_Opart[obase + r2 * 64 + c0] = acc[nt][2];
        g_Opart[obase + r2 * 64 + c0 + 1] = acc[nt][3];
    }
    if (t < 64) {
        size_t mbase = (((size_t)h * 32 + rt) * 4 + ci) * 64 + t;
        g_mpart[mbase] = m_s[t];
        g_lpart[mbase] = l_s[t];
    }
}

// ---------------- merge partials + analytic tail + normalize ----------------
__global__ void __launch_bounds__(256) k_fmerge() {
    int rt = blockIdx.x, h = blockIdx.y;
    int nch = rt / 8 + 1;
    int bm = rt * 64;
    int t = threadIdx.x;
    int row = t >> 2, seg = t & 3;

    size_t pbase = ((size_t)h * 32 + rt) * 4;
    float mv[4], lv[4];
    float mstar = -1e30f;
#pragma unroll
    for (int ci = 0; ci < 4; ci++) {
        if (ci < nch) {
            mv[ci] = g_mpart[(pbase + ci) * 64 + row];
            lv[ci] = g_lpart[(pbase + ci) * 64 + row];
            mstar = fmaxf(mstar, mv[ci]);
        }
    }
    float p0 = __expf(-mstar);
    float nz = (float)(LV - (bm + 64));
    float lstar = nz * p0;
    float w[4];
#pragma unroll
    for (int ci = 0; ci < 4; ci++) {
        if (ci < nch) {
            w[ci] = __expf(mv[ci] - mstar);
            lstar += lv[ci] * w[ci];
        }
    }
    float inv = 1.f / lstar;

    int tb = rt + 1;
    const float* suf = g_vsuf + ((size_t)h * 33 + tb) * DK + seg * 16;
    float o[16];
#pragma unroll
    for (int q4 = 0; q4 < 4; q4++) {
        float4 sv = *(const float4*)(suf + q4 * 4);
        o[q4 * 4 + 0] = p0 * sv.x;
        o[q4 * 4 + 1] = p0 * sv.y;
        o[q4 * 4 + 2] = p0 * sv.z;
        o[q4 * 4 + 3] = p0 * sv.w;
    }
#pragma unroll
    for (int ci = 0; ci < 4; ci++) {
        if (ci < nch) {
            const float* op = g_Opart + (pbase + ci) * 4096 + row * 64 + seg * 16;
            float wc = w[ci];
#pragma unroll
            for (int q4 = 0; q4 < 4; q4++) {
                float4 ov = *(const float4*)(op + q4 * 4);
                o[q4 * 4 + 0] += wc * ov.x;
                o[q4 * 4 + 1] += wc * ov.y;
                o[q4 * 4 + 2] += wc * ov.z;
                o[q4 * 4 + 3] += wc * ov.w;
            }
        }
    }
    float* dst = g_att + (size_t)(bm + row) * D + h * DK + seg * 16;
#pragma unroll
    for (int q4 = 0; q4 < 4; q4++)
        *(float4*)(dst + q4 * 4) = make_float4(o[q4 * 4 + 0] * inv, o[q4 * 4 + 1] * inv,
                                               o[q4 * 4 + 2] * inv, o[q4 * 4 + 3] * inv);
}

// ---------------- residual + pos + LN2 ----------------
__device__ __forceinline__ float sine_pos_elem(float xe, int i) {
    const float L2_1E4 = 13.287712379549449f;
    int j = i >> 1;
    float dim = exp2f(((float)j / 256.f) * L2_1E4);
    float val = xe / dim;
    return (i & 1) ? cosf(val) : sinf(val);
}

__global__ void k_res_ln2(const float* __restrict__ w, const float* __restrict__ b) {
    int r = blockIdx.x;
    __shared__ float sh[32];
    int i0 = threadIdx.x, i1 = threadIdx.x + 256;
    size_t o = (size_t)r * D;
    float v0, v1;
    if (r < LV) {
        v0 = g_src[o + i0] + g_proj[o + i0] + g_posq[o + i0];
        v1 = g_src[o + i1] + g_proj[o + i1] + g_posq[o + i1];
    } else {
        int tt = r - LV;
        float xe = (float)(tt + 1) / (512.f + 1e-6f) * 6.283185307179586f;
        v0 = g_src[o + i0] + g_src2[o + i0] + sine_pos_elem(xe, i0);
        v1 = g_src[o + i1] + g_src2[o + i1] + sine_pos_elem(xe, i1);
    }
    float s = blk_sum(v0 + v1, sh);
    float s2 = blk_sum(v0 * v0 + v1 * v1, sh);
    float mu = s * (1.f / D);
    float var = s2 * (1.f / D) - mu * mu;
    float inv = rsqrtf(var + 1e-5f);
    g_src[o + i0] = v0;
    g_src[o + i1] = v1;
    g_src2[o + i0] = (v0 - mu) * inv * w[i0] + b[i0];
    g_src2[o + i1] = (v1 - mu) * inv * w[i1] + b[i1];
}

// ---------------- residual + LN3 + output ----------------
__global__ void k_res_ln3(const float* __restrict__ w, const float* __restrict__ b,
                          float* __restrict__ out) {
    int r = blockIdx.x;
    __shared__ float sh[32];
    int i0 = threadIdx.x, i1 = threadIdx.x + 256;
    size_t o = (size_t)r * D;
    float v0 = g_src[o + i0] + g_proj[o + i0];
    float v1 = g_src[o + i1] + g_proj[o + i1];
    float s = blk_sum(v0 + v1, sh);
    float s2 = blk_sum(v0 * v0 + v1 * v1, sh);
    float mu = s * (1.f / D);
    float var = s2 * (1.f / D) - mu * mu;
    float inv = rsqrtf(var + 1e-5f);
    out[o + i0] = (v0 - mu) * inv * w[i0] + b[i0];
    out[o + i1] = (v1 - mu) * inv * w[i1] + b[i1];
}

extern "C" void kernel_launch(void* const* d_in, const int* in_sizes, int n_in,
                              void* d_out, int out_size) {
    const float* src_vid = (const float*)d_in[0];
    const float* src_txt = (const float*)d_in[1];
    const float* ln1_w = (const float*)d_in[2];
    const float* ln1_b = (const float*)d_in[3];
    const float* wq = (const float*)d_in[4];
    const float* bq = (const float*)d_in[5];
    const float* wk = (const float*)d_in[6];
    const float* bk = (const float*)d_in[7];
    const float* wv = (const float*)d_in[8];
    const float* bv = (const float*)d_in[9];
    const float* wo = (const float*)d_in[10];
    const float* bo = (const float*)d_in[11];
    const float* lin1_w = (const float*)d_in[12];
    const float* lin1_b = (const float*)d_in[13];
    const float* lin2_w = (const float*)d_in[14];
    const float* lin2_b = (const float*)d_in[15];
    const float* ln2_w = (const float*)d_in[16];
    const float* ln2_b = (const float*)d_in[17];
    const float* ln3_w = (const float*)d_in[18];
    const float* ln3_b = (const float*)d_in[19];
    const float* learn = (const float*)d_in[20];
    float* out = (float*)d_out;

    cudaFuncSetAttribute(k_flash_chunk, cudaFuncAttributeMaxDynamicSharedMemorySize,
                         FL_SMEM_BYTES);

    k_mask<<<LV, 256>>>(learn);
    k_loss<<<1, 256>>>(out, out_size);
    k_ln1<<<LTOT, 256>>>(src_vid, src_txt, ln1_w, ln1_b);
    k_pos<<<LV, 256>>>(src_vid);

    k_gemm_qkv<<<dim3(D / 64, LV / 128, 3), 256>>>(wq, bq, wk, bk, wv, bv);

    k_vsuf<<<dim3(32, H), 256>>>();
    k_vtrans<<<dim3(LV / 64, H), 256>>>();
    k_flash_chunk<<<dim3(80, H), 256, FL_SMEM_BYTES>>>();
    k_fmerge<<<dim3(32, H), 256>>>();

    k_gemm_o<<<dim3(D / 64, LV / 128), 256>>>(wo, bo);
    k_res_ln2<<<LTOT, 256>>>(ln2_w, ln2_b);

    k_gemm_f1<<<dim3(FF / 64, LTOT / 128), 256>>>(lin1_w, lin1_b);
    k_gemm_f2<<<dim3(D / 64, LTOT / 128), 256>>>(lin2_w, lin2_b);

    k_res_ln3<<<LTOT, 256>>>(ln3_w, ln3_b, out);
}